// round 6
// baseline (speedup 1.0000x reference)
#include <cuda_runtime.h>

#define NB_DIMS 128
#define BATCH   16384

// One warp per sample. 512MB table => row byte offsets fit in u32, so the
// idx->address chain is a single IMAD. Rows are zero-reuse: stream them
// (__ldcs) so L2 keeps the index array hot for later waves instead.
__global__ void __launch_bounds__(128) sgns_dot_kernel(
    const int*   __restrict__ vii,   // [BATCH, 2] int32
    const float* __restrict__ W,     // [NB_VECS, 128] f32
    float*       __restrict__ out)   // [BATCH] f32
{
    int gtid = blockIdx.x * blockDim.x + threadIdx.x;
    int warp = gtid >> 5;
    int lane = gtid & 31;
    if (warp >= BATCH) return;

    // Both indices in one broadcast 8B load.
    int2 idx = __ldg(reinterpret_cast<const int2*>(vii) + warp);

    const char* Wb = reinterpret_cast<const char*>(W);
    unsigned off0 = (unsigned)idx.x * (unsigned)(NB_DIMS * 4) + (unsigned)(lane * 16);
    unsigned off1 = (unsigned)idx.y * (unsigned)(NB_DIMS * 4) + (unsigned)(lane * 16);

    // Two independent 16B streaming gathers (evict-first: zero reuse).
    float4 a = __ldcs(reinterpret_cast<const float4*>(Wb + off0));
    float4 b = __ldcs(reinterpret_cast<const float4*>(Wb + off1));

    float s = a.x * b.x + a.y * b.y + a.z * b.z + a.w * b.w;

    #pragma unroll
    for (int o = 16; o > 0; o >>= 1)
        s += __shfl_down_sync(0xffffffffu, s, o);

    if (lane == 0) out[warp] = s;
}

extern "C" void kernel_launch(void* const* d_in, const int* in_sizes, int n_in,
                              void* d_out, int out_size)
{
    const void* p0 = d_in[0];
    const void* p1 = d_in[1];
    const int*   vii;
    const float* W;
    if (in_sizes[0] < in_sizes[1]) {
        vii = (const int*)p0;  W = (const float*)p1;
    } else {
        vii = (const int*)p1;  W = (const float*)p0;
    }
    float* out = (float*)d_out;

    const int threads = 128;                       // 4 warps/block: finer packing
    const int blocks  = (BATCH * 32) / threads;    // 4096 blocks
    sgns_dot_kernel<<<blocks, threads>>>(vii, W, out);
}

// round 8
// speedup vs baseline: 1.3478x; 1.3478x over previous
#include <cuda_runtime.h>

#define NB_DIMS   128
#define BATCH     16384
#define NBLOCKS   1184                 // 148 SMs x 8 blocks -> exactly one wave
#define NWARPS    (NBLOCKS * 8)       // 9472 warps

// Single-wave persistent layout: warp w handles samples w and w+NWARPS.
// Both index pairs and all four row gathers are independent and issue
// before any consumption. No shuffles in the prologue, regs kept <= 32.
__global__ void __launch_bounds__(256, 8) sgns_dot_kernel(
    const int*   __restrict__ vii,   // [BATCH, 2] int32
    const float* __restrict__ W,     // [NB_VECS, 128] f32
    float*       __restrict__ out)   // [BATCH] f32
{
    int gtid = blockIdx.x * blockDim.x + threadIdx.x;
    int warp = gtid >> 5;
    int lane = gtid & 31;

    int s0 = warp;                 // always < BATCH (NWARPS < BATCH)
    int s1 = warp + NWARPS;        // may be >= BATCH
    bool has2 = (s1 < BATCH);

    // Two independent broadcast idx loads (8B each).
    int2 ia = __ldg(reinterpret_cast<const int2*>(vii) + s0);
    int2 ib = has2 ? __ldg(reinterpret_cast<const int2*>(vii) + s1)
                   : make_int2(0, 0);   // row 0 is always safe to read

    const char* Wb = reinterpret_cast<const char*>(W);
    unsigned lb  = (unsigned)(lane * 16);
    unsigned o0a = (unsigned)ia.x * 512u + lb;
    unsigned o0b = (unsigned)ia.y * 512u + lb;
    unsigned o1a = (unsigned)ib.x * 512u + lb;
    unsigned o1b = (unsigned)ib.y * 512u + lb;

    // Four independent 16B gathers, all in flight before any FMA.
    float4 a0 = __ldg(reinterpret_cast<const float4*>(Wb + o0a));
    float4 b0 = __ldg(reinterpret_cast<const float4*>(Wb + o0b));
    float4 a1 = __ldg(reinterpret_cast<const float4*>(Wb + o1a));
    float4 b1 = __ldg(reinterpret_cast<const float4*>(Wb + o1b));

    float r0 = a0.x * b0.x + a0.y * b0.y + a0.z * b0.z + a0.w * b0.w;
    float r1 = a1.x * b1.x + a1.y * b1.y + a1.z * b1.z + a1.w * b1.w;

    #pragma unroll
    for (int o = 16; o > 0; o >>= 1) {
        r0 += __shfl_xor_sync(0xffffffffu, r0, o);
        r1 += __shfl_xor_sync(0xffffffffu, r1, o);
    }

    if (lane == 0) {
        out[s0] = r0;
        if (has2) out[s1] = r1;
    }
}

extern "C" void kernel_launch(void* const* d_in, const int* in_sizes, int n_in,
                              void* d_out, int out_size)
{
    const void* p0 = d_in[0];
    const void* p1 = d_in[1];
    const int*   vii;
    const float* W;
    if (in_sizes[0] < in_sizes[1]) {
        vii = (const int*)p0;  W = (const float*)p1;
    } else {
        vii = (const int*)p1;  W = (const float*)p0;
    }
    float* out = (float*)d_out;

    sgns_dot_kernel<<<NBLOCKS, 256>>>(vii, W, out);
}